// round 1
// baseline (speedup 1.0000x reference)
#include <cuda_runtime.h>
#include <cuda_bf16.h>
#include <math.h>

// ---------------------------------------------------------------------------
// LinearSelfAttention: qkv GEMM -> RoPE -> ELU+1 feature map -> linear attn
// (kv = K^T V, k_sum, out = Q kv / (Q . k_sum)) -> output GEMM.
// Shapes: B=4, T=4096, D=1024, H=16, hd=64.
// Round 1: fp32 SIMT implementation, 128x128x16 tiled GEMMs.
// ---------------------------------------------------------------------------

#define B_   4
#define T_   4096
#define D_   1024
#define H_   16
#define HD_  64
#define M_   (B_ * T_)            // 16384
#define PAIRS (B_ * H_)           // 64
#define NCHUNK 16                 // T-chunks for kv reduction
#define ROWS_PER_CHUNK (T_ / NCHUNK)  // 256

// ------------------------- scratch (device globals) ------------------------
__device__ float g_qkv[(size_t)M_ * 3 * D_];           // 192 MB  [m, 3D]
__device__ float g_qf[(size_t)PAIRS * T_ * HD_];       // 64 MB   [pair, t, d]
__device__ float g_kf[(size_t)PAIRS * T_ * HD_];       // 64 MB
__device__ float g_attn[(size_t)M_ * D_];              // 64 MB   [b, t, h*hd]
__device__ float g_kvpart[(size_t)NCHUNK * PAIRS * HD_ * HD_];  // 16 MB
__device__ float g_kspart[(size_t)NCHUNK * PAIRS * HD_];
__device__ float g_kv[(size_t)PAIRS * HD_ * HD_];      // [pair, d, v]
__device__ float g_ksum[(size_t)PAIRS * HD_];

// inv_freq[i] = 10000^(-2i/64) = 10^(-i/8), exact decimal literals -> the
// compiler rounds each to the nearest fp32 (matches jax fp32 pow to <=~1ulp).
__constant__ float c_invfreq[32] = {
    1.0f, 0.7498942093324559f, 0.5623413251903491f, 0.4216965034285822f,
    0.31622776601683794f, 0.23713737056616552f, 0.1778279410038923f,
    0.13335214321633242f,
    0.1f, 0.07498942093324558f, 0.05623413251903491f, 0.04216965034285822f,
    0.03162277660168379f, 0.023713737056616554f, 0.01778279410038923f,
    0.013335214321633242f,
    0.01f, 0.007498942093324559f, 0.005623413251903491f, 0.004216965034285822f,
    0.0031622776601683794f, 0.0023713737056616554f, 0.001778279410038923f,
    0.0013335214321633242f,
    0.001f, 0.0007498942093324559f, 0.0005623413251903491f,
    0.0004216965034285822f, 0.00031622776601683794f, 0.00023713737056616554f,
    0.0001778279410038923f, 0.00013335214321633243f
};

// ------------------------- GEMM: C[M,N] = A[M,K] * B[N,K]^T -----------------
// 128x128 block tile, 8x8 per thread, K-tile 16, fp32.
#define TM 128
#define TN 128
#define TK 16
#define LDA_S (TM + 4)

__global__ __launch_bounds__(256, 2)
void gemm_nt(const float* __restrict__ A, const float* __restrict__ Bm,
             float* __restrict__ C, int M, int N, int K)
{
    __shared__ float As[TK][LDA_S];
    __shared__ float Bs[TK][LDA_S];

    const int tid = threadIdx.x;
    const int tx = tid & 15;          // 0..15 (N dir)
    const int ty = tid >> 4;          // 0..15 (M dir)
    const int lrow = tid >> 2;        // 0..63, loader row
    const int lk = (tid & 3) * 4;     // 0,4,8,12 loader k-offset

    const float* Ab = A + (size_t)blockIdx.y * TM * K;
    const float* Bb = Bm + (size_t)blockIdx.x * TN * K;

    float acc[8][8];
    #pragma unroll
    for (int i = 0; i < 8; i++)
        #pragma unroll
        for (int j = 0; j < 8; j++) acc[i][j] = 0.0f;

    for (int k0 = 0; k0 < K; k0 += TK) {
        #pragma unroll
        for (int r = 0; r < 2; r++) {
            int row = lrow + 64 * r;
            float4 va = *(const float4*)(Ab + (size_t)row * K + k0 + lk);
            As[lk + 0][row] = va.x;
            As[lk + 1][row] = va.y;
            As[lk + 2][row] = va.z;
            As[lk + 3][row] = va.w;
            float4 vb = *(const float4*)(Bb + (size_t)row * K + k0 + lk);
            Bs[lk + 0][row] = vb.x;
            Bs[lk + 1][row] = vb.y;
            Bs[lk + 2][row] = vb.z;
            Bs[lk + 3][row] = vb.w;
        }
        __syncthreads();

        #pragma unroll
        for (int kk = 0; kk < TK; kk++) {
            float a[8], b[8];
            *(float4*)&a[0] = *(const float4*)&As[kk][ty * 8];
            *(float4*)&a[4] = *(const float4*)&As[kk][ty * 8 + 4];
            *(float4*)&b[0] = *(const float4*)&Bs[kk][tx * 8];
            *(float4*)&b[4] = *(const float4*)&Bs[kk][tx * 8 + 4];
            #pragma unroll
            for (int i = 0; i < 8; i++)
                #pragma unroll
                for (int j = 0; j < 8; j++)
                    acc[i][j] = fmaf(a[i], b[j], acc[i][j]);
        }
        __syncthreads();
    }

    float* Cp = C + (size_t)(blockIdx.y * TM + ty * 8) * N + blockIdx.x * TN + tx * 8;
    #pragma unroll
    for (int i = 0; i < 8; i++) {
        float4 v0 = make_float4(acc[i][0], acc[i][1], acc[i][2], acc[i][3]);
        float4 v1 = make_float4(acc[i][4], acc[i][5], acc[i][6], acc[i][7]);
        *(float4*)(Cp + (size_t)i * N) = v0;
        *(float4*)(Cp + (size_t)i * N + 4) = v1;
    }
}

// ------------------------- RoPE + feature map -------------------------------
// One thread per (pair, t, i) with i in [0,32). Reads q/k halves from g_qkv,
// writes q_feat/k_feat in [pair, t, d] layout.
__global__ __launch_bounds__(256)
void rope_feat_kernel(const float* __restrict__ qkv,
                      float* __restrict__ qf, float* __restrict__ kf)
{
    int idx = blockIdx.x * blockDim.x + threadIdx.x;  // 64*4096*32 threads
    int i = idx & 31;
    int t = (idx >> 5) & (T_ - 1);
    int pair = idx >> 17;
    int b = pair >> 4;
    int h = pair & 15;

    size_t base = ((size_t)(b * T_ + t)) * (3 * D_) + h * HD_;
    float qe = qkv[base + i];
    float qo = qkv[base + i + 32];
    float ke = qkv[base + D_ + i];
    float ko = qkv[base + D_ + i + 32];

    float ang = (float)t * c_invfreq[i];
    float s, c;
    sincosf(ang, &s, &c);

    float qre = qe * c - qo * s;
    float qro = qe * s + qo * c;
    float kre = ke * c - ko * s;
    float kro = ke * s + ko * c;

    const float scale = 0.125f;   // hd^-0.5
    qre *= scale; qro *= scale;

    // feat(x) = elu(x) + 1  ==  x>0 ? x+1 : expm1(x)+1   (mirror jax exactly)
    float fqe = qre > 0.0f ? qre + 1.0f : expm1f(qre) + 1.0f;
    float fqo = qro > 0.0f ? qro + 1.0f : expm1f(qro) + 1.0f;
    float fke = kre > 0.0f ? kre + 1.0f : expm1f(kre) + 1.0f;
    float fko = kro > 0.0f ? kro + 1.0f : expm1f(kro) + 1.0f;

    size_t ob = ((size_t)pair * T_ + t) * HD_;
    qf[ob + i]      = fqe;
    qf[ob + i + 32] = fqo;
    kf[ob + i]      = fke;
    kf[ob + i + 32] = fko;
}

// ------------------------- kv = K^T V, k_sum (partials) ---------------------
// grid (NCHUNK, PAIRS); 256 threads as 16x16; each thread owns a 4x4 tile of
// the 64x64 kv accumulator. Deterministic: partials written per chunk.
__global__ __launch_bounds__(256)
void kv_ksum_kernel(const float* __restrict__ kf, const float* __restrict__ qkv,
                    float* __restrict__ kvpart, float* __restrict__ kspart)
{
    __shared__ float ks[32][64];
    __shared__ float vs[32][64];

    const int pair = blockIdx.y;
    const int chunk = blockIdx.x;
    const int b = pair >> 4;
    const int h = pair & 15;
    const int tid = threadIdx.x;
    const int tx = tid & 15;          // v dir
    const int ty = tid >> 4;          // d dir

    const float* kbase = kf + ((size_t)pair * T_ + chunk * ROWS_PER_CHUNK) * HD_;
    const float* vbase = qkv + ((size_t)(b * T_ + chunk * ROWS_PER_CHUNK)) * (3 * D_)
                         + 2 * D_ + h * HD_;

    float acc[4][4];
    #pragma unroll
    for (int i = 0; i < 4; i++)
        #pragma unroll
        for (int j = 0; j < 4; j++) acc[i][j] = 0.0f;
    float ksl[4] = {0.0f, 0.0f, 0.0f, 0.0f};

    for (int tile = 0; tile < ROWS_PER_CHUNK / 32; tile++) {
        #pragma unroll
        for (int l = 0; l < 2; l++) {
            int fi = tid + l * 256;
            int row = fi >> 4;                 // 0..31
            int c4 = (fi & 15) * 4;
            *(float4*)&ks[row][c4] =
                *(const float4*)(kbase + (size_t)(tile * 32 + row) * HD_ + c4);
            *(float4*)&vs[row][c4] =
                *(const float4*)(vbase + (size_t)(tile * 32 + row) * (3 * D_) + c4);
        }
        __syncthreads();

        #pragma unroll
        for (int r = 0; r < 32; r++) {
            float ka[4], va[4];
            *(float4*)ka = *(const float4*)&ks[r][ty * 4];
            *(float4*)va = *(const float4*)&vs[r][tx * 4];
            #pragma unroll
            for (int i = 0; i < 4; i++)
                #pragma unroll
                for (int j = 0; j < 4; j++)
                    acc[i][j] = fmaf(ka[i], va[j], acc[i][j]);
            if (ty == 0) {
                #pragma unroll
                for (int j = 0; j < 4; j++)
                    ksl[j] += ks[r][tx * 4 + j];
            }
        }
        __syncthreads();
    }

    float* kvp = kvpart + (size_t)chunk * (PAIRS * HD_ * HD_) + (size_t)pair * HD_ * HD_;
    #pragma unroll
    for (int i = 0; i < 4; i++)
        #pragma unroll
        for (int j = 0; j < 4; j++)
            kvp[(ty * 4 + i) * HD_ + tx * 4 + j] = acc[i][j];
    if (ty == 0) {
        float* ksp = kspart + (size_t)chunk * (PAIRS * HD_) + pair * HD_;
        #pragma unroll
        for (int j = 0; j < 4; j++) ksp[tx * 4 + j] = ksl[j];
    }
}

// fixed-order reduction of the NCHUNK partials
__global__ __launch_bounds__(256)
void reduce_kv_kernel(const float* __restrict__ kvpart, const float* __restrict__ kspart,
                      float* __restrict__ kv, float* __restrict__ ksum)
{
    int i = blockIdx.x * blockDim.x + threadIdx.x;   // 64*64*64 = 262144
    float s = 0.0f;
    #pragma unroll
    for (int c = 0; c < NCHUNK; c++)
        s += kvpart[(size_t)c * (PAIRS * HD_ * HD_) + i];
    kv[i] = s;
    if (i < PAIRS * HD_) {
        float s2 = 0.0f;
        #pragma unroll
        for (int c = 0; c < NCHUNK; c++)
            s2 += kspart[(size_t)c * (PAIRS * HD_) + i];
        ksum[i] = s2;
    }
}

// ------------------------- out = (Q kv) / max(Q.ksum, 1e-6) -----------------
// grid (T/32, PAIRS); 256 threads = 32 t-rows x 8 v-groups of 8.
__global__ __launch_bounds__(256)
void attn_out_kernel(const float* __restrict__ qf, const float* __restrict__ kv,
                     const float* __restrict__ ksum, float* __restrict__ attn)
{
    __shared__ float kv_s[HD_][HD_];
    __shared__ float q_s[32][HD_];
    __shared__ float ksum_s[HD_];

    const int pair = blockIdx.y;
    const int t0 = blockIdx.x * 32;
    const int b = pair >> 4;
    const int h = pair & 15;
    const int tid = threadIdx.x;
    const int row = tid >> 3;
    const int tx = tid & 7;

    const float4* kvp = (const float4*)(kv + (size_t)pair * HD_ * HD_);
    #pragma unroll
    for (int l = 0; l < 4; l++)
        ((float4*)kv_s)[tid + l * 256] = kvp[tid + l * 256];
    if (tid < 16)
        ((float4*)ksum_s)[tid] = ((const float4*)(ksum + pair * HD_))[tid];
    const float4* qp = (const float4*)(qf + ((size_t)pair * T_ + t0) * HD_);
    #pragma unroll
    for (int l = 0; l < 2; l++)
        ((float4*)q_s)[tid + l * 256] = qp[tid + l * 256];
    __syncthreads();

    float acc[8] = {0, 0, 0, 0, 0, 0, 0, 0};
    float den = 0.0f;
    #pragma unroll
    for (int d = 0; d < HD_; d++) {
        float qd = q_s[row][d];
        den = fmaf(qd, ksum_s[d], den);
        float4 k0 = *(const float4*)&kv_s[d][tx * 8];
        float4 k1 = *(const float4*)&kv_s[d][tx * 8 + 4];
        acc[0] = fmaf(qd, k0.x, acc[0]);
        acc[1] = fmaf(qd, k0.y, acc[1]);
        acc[2] = fmaf(qd, k0.z, acc[2]);
        acc[3] = fmaf(qd, k0.w, acc[3]);
        acc[4] = fmaf(qd, k1.x, acc[4]);
        acc[5] = fmaf(qd, k1.y, acc[5]);
        acc[6] = fmaf(qd, k1.z, acc[6]);
        acc[7] = fmaf(qd, k1.w, acc[7]);
    }
    float inv = 1.0f / fmaxf(den, 1e-6f);

    float* op = attn + ((size_t)(b * T_ + t0 + row)) * D_ + h * HD_ + tx * 8;
    *(float4*)op = make_float4(acc[0] * inv, acc[1] * inv, acc[2] * inv, acc[3] * inv);
    *(float4*)(op + 4) = make_float4(acc[4] * inv, acc[5] * inv, acc[6] * inv, acc[7] * inv);
}

// ------------------------- launch ------------------------------------------
static float* sym_addr(const void* symbol)
{
    void* p = nullptr;
    cudaGetSymbolAddress(&p, symbol);
    return (float*)p;
}

extern "C" void kernel_launch(void* const* d_in, const int* in_sizes, int n_in,
                              void* d_out, int out_size)
{
    (void)in_sizes; (void)n_in; (void)out_size;
    const float* x     = (const float*)d_in[0];   // [B,T,D]
    const float* w_qkv = (const float*)d_in[1];   // [3D,D]
    const float* w_out = (const float*)d_in[2];   // [D,D]
    float* out = (float*)d_out;                   // [B,T,D]

    float* qkv   = sym_addr(g_qkv);
    float* qf    = sym_addr(g_qf);
    float* kf    = sym_addr(g_kf);
    float* attn  = sym_addr(g_attn);
    float* kvprt = sym_addr(g_kvpart);
    float* ksprt = sym_addr(g_kspart);
    float* kv    = sym_addr(g_kv);
    float* ksum  = sym_addr(g_ksum);

    // 1) qkv = x @ w_qkv^T   [16384, 3072]
    gemm_nt<<<dim3(3 * D_ / TN, M_ / TM), 256>>>(x, w_qkv, qkv, M_, 3 * D_, D_);

    // 2) RoPE + ELU feature map -> q_feat, k_feat
    rope_feat_kernel<<<(PAIRS * T_ * 32) / 256, 256>>>(qkv, qf, kf);

    // 3) kv = K^T V and k_sum (chunked partials, then fixed-order reduce)
    kv_ksum_kernel<<<dim3(NCHUNK, PAIRS), 256>>>(kf, qkv, kvprt, ksprt);
    reduce_kv_kernel<<<(PAIRS * HD_ * HD_) / 256, 256>>>(kvprt, ksprt, kv, ksum);

    // 4) out_head = (Q kv) / denom  -> [B,T,D] layout
    attn_out_kernel<<<dim3(T_ / 32, PAIRS), 256>>>(qf, kv, ksum, attn);

    // 5) out = attn @ w_out^T   [16384, 1024]
    gemm_nt<<<dim3(D_ / TN, M_ / TM), 256>>>(attn, w_out, out, M_, D_, D_);
}

// round 3
// speedup vs baseline: 1.7724x; 1.7724x over previous
#include <cuda_runtime.h>
#include <cuda_bf16.h>
#include <math.h>
#include <stdint.h>

// ---------------------------------------------------------------------------
// LinearSelfAttention, Round 3: mma.sync (HMMA) bf16 hi/lo 3-pass GEMMs.
// Target is plain sm_100 (no 'a' feature) -> no tcgen05; use portable
// ldmatrix + mma.sync.m16n8k16 + cp.async.
// Shapes: B=4, T=4096, D=1024, H=16, hd=64.
// ---------------------------------------------------------------------------

#define B_   4
#define T_   4096
#define D_   1024
#define H_   16
#define HD_  64
#define M_   (B_ * T_)            // 16384
#define PAIRS (B_ * H_)           // 64
#define NCHUNK 16
#define ROWS_PER_CHUNK (T_ / NCHUNK)
#define GK 1024                   // GEMM K dim (fixed)

// ------------------------- scratch (device globals) ------------------------
__device__ float g_qkv[(size_t)M_ * 3 * D_];           // 192 MB
__device__ float g_qf[(size_t)PAIRS * T_ * HD_];       // 64 MB
__device__ float g_kf[(size_t)PAIRS * T_ * HD_];       // 64 MB
__device__ float g_attn[(size_t)M_ * D_];              // 64 MB
__device__ float g_kvpart[(size_t)NCHUNK * PAIRS * HD_ * HD_];
__device__ float g_kspart[(size_t)NCHUNK * PAIRS * HD_];
__device__ float g_kv[(size_t)PAIRS * HD_ * HD_];
__device__ float g_ksum[(size_t)PAIRS * HD_];
__device__ __nv_bfloat16 g_ahi[(size_t)M_ * D_];       // 32 MB
__device__ __nv_bfloat16 g_alo[(size_t)M_ * D_];       // 32 MB
__device__ __nv_bfloat16 g_bhi[(size_t)3 * D_ * D_];   // 6 MB
__device__ __nv_bfloat16 g_blo[(size_t)3 * D_ * D_];   // 6 MB

__constant__ float c_invfreq[32] = {
    1.0f, 0.7498942093324559f, 0.5623413251903491f, 0.4216965034285822f,
    0.31622776601683794f, 0.23713737056616552f, 0.1778279410038923f,
    0.13335214321633242f,
    0.1f, 0.07498942093324558f, 0.05623413251903491f, 0.04216965034285822f,
    0.03162277660168379f, 0.023713737056616554f, 0.01778279410038923f,
    0.013335214321633242f,
    0.01f, 0.007498942093324559f, 0.005623413251903491f, 0.004216965034285822f,
    0.0031622776601683794f, 0.0023713737056616554f, 0.001778279410038923f,
    0.0013335214321633242f,
    0.001f, 0.0007498942093324559f, 0.0005623413251903491f,
    0.0004216965034285822f, 0.00031622776601683794f, 0.00023713737056616554f,
    0.0001778279410038923f, 0.00013335214321633243f
};

// ------------------------- PTX helpers --------------------------------------
__device__ __forceinline__ uint32_t smem_u32(const void* p) {
    uint32_t a;
    asm("{ .reg .u64 t; cvta.to.shared.u64 t, %1; cvt.u32.u64 %0, t; }"
        : "=r"(a) : "l"(p));
    return a;
}
__device__ __forceinline__ void cpasync16(uint32_t s, const void* g) {
    asm volatile("cp.async.cg.shared.global [%0], [%1], 16;" :: "r"(s), "l"(g));
}
#define CP_COMMIT() asm volatile("cp.async.commit_group;" ::: "memory")
#define CP_WAIT1()  asm volatile("cp.async.wait_group 1;" ::: "memory")
#define CP_WAIT0()  asm volatile("cp.async.wait_group 0;" ::: "memory")

__device__ __forceinline__ void ldsm4(uint32_t* r, uint32_t addr) {
    asm volatile("ldmatrix.sync.aligned.m8n8.x4.shared.b16 {%0,%1,%2,%3}, [%4];"
        : "=r"(r[0]), "=r"(r[1]), "=r"(r[2]), "=r"(r[3]) : "r"(addr));
}
__device__ __forceinline__ void mma16816(float* d, const uint32_t* a,
                                         const uint32_t* b) {
    asm volatile("mma.sync.aligned.m16n8k16.row.col.f32.bf16.bf16.f32 "
        "{%0,%1,%2,%3}, {%4,%5,%6,%7}, {%8,%9}, {%0,%1,%2,%3};"
        : "+f"(d[0]), "+f"(d[1]), "+f"(d[2]), "+f"(d[3])
        : "r"(a[0]), "r"(a[1]), "r"(a[2]), "r"(a[3]), "r"(b[0]), "r"(b[1]));
}

// ------------------------- MMA GEMM: C = A * B^T ----------------------------
// A[M,K], B[N,K] row-major bf16 (hi/lo pairs); C[M,N] fp32.
// Block 128x128, 8 warps (4M x 2N), warp tile 32x64, K-step 16, 2-stage.
#define RS 24                       // smem row stride (bf16), 48 B: conflict-free
#define OP_ELEMS (128 * RS)         // 3072 bf16 = 6144 B per operand tile
#define STAGE_B (4 * OP_ELEMS * 2)  // 24576 B
#define OFF_AHI 0
#define OFF_ALO (OP_ELEMS * 2)
#define OFF_BHI (2 * OP_ELEMS * 2)
#define OFF_BLO (3 * OP_ELEMS * 2)

__global__ void __launch_bounds__(256, 1)
gemm_mma(const __nv_bfloat16* __restrict__ Ahi, const __nv_bfloat16* __restrict__ Alo,
         const __nv_bfloat16* __restrict__ Bhi, const __nv_bfloat16* __restrict__ Blo,
         float* __restrict__ C, int N)
{
    __shared__ __nv_bfloat16 smem[2][4][OP_ELEMS];   // 49152 B

    const int tid = threadIdx.x;
    const int l = tid & 31;
    const int w = tid >> 5;
    const int mw = w >> 1;                 // 0..3
    const int nw = w & 1;                  // 0..1
    const long rowA0 = (long)blockIdx.y * 128;
    const long rowB0 = (long)blockIdx.x * 128;

    // ---- loader mapping: each thread copies 4x16B (one per operand) -------
    const int lrow = tid >> 1;             // 0..127
    const int lhalf = (tid & 1) * 8;       // bf16 element offset within k16
    const __nv_bfloat16* gsrc[4] = {
        Ahi + (rowA0 + lrow) * GK + lhalf,
        Alo + (rowA0 + lrow) * GK + lhalf,
        Bhi + (rowB0 + lrow) * GK + lhalf,
        Blo + (rowB0 + lrow) * GK + lhalf };
    uint32_t sdst0 = smem_u32(&smem[0][0][lrow * RS]) + lhalf * 2;

    float acc[2][8][4];
    #pragma unroll
    for (int i = 0; i < 2; i++)
        #pragma unroll
        for (int j = 0; j < 8; j++)
            #pragma unroll
            for (int k = 0; k < 4; k++) acc[i][j][k] = 0.0f;

    // ---- ldmatrix source addresses (stage-0 based) ------------------------
    const uint32_t sbase = smem_u32(&smem[0][0][0]);
    // A: lanes 0-15 -> rows 0-15 (k-offset 0), lanes 16-31 -> same rows, k+8
    uint32_t aoffA = (uint32_t)(((mw * 32 + (l & 15)) * RS + (l >> 4) * 8) * 2);
    // B: n = (l&7) + ((l>>4)<<3), k-offset = ((l>>3)&1)*8
    uint32_t aoffB = (uint32_t)((((nw * 64 + (l & 7) + ((l >> 4) << 3)) * RS
                                  + ((l >> 3) & 1) * 8)) * 2);

    // ---- prefetch stage 0 --------------------------------------------------
    #pragma unroll
    for (int o = 0; o < 4; o++)
        cpasync16(sdst0 + o * (OP_ELEMS * 2), gsrc[o]);
    CP_COMMIT();

    const int NITER = GK / 16;             // 64
    for (int c = 0; c < NITER; c++) {
        if (c + 1 < NITER) {
            const int nb = (c + 1) & 1;
            const int k0 = (c + 1) * 16;
            #pragma unroll
            for (int o = 0; o < 4; o++)
                cpasync16(sdst0 + nb * STAGE_B + o * (OP_ELEMS * 2), gsrc[o] + k0);
            CP_COMMIT();
            CP_WAIT1();
        } else {
            CP_WAIT0();
        }
        __syncthreads();

        const uint32_t stb = sbase + (c & 1) * STAGE_B;

        uint32_t ah[2][4], al[2][4];
        #pragma unroll
        for (int mt = 0; mt < 2; mt++) {
            uint32_t ao = stb + aoffA + (uint32_t)(mt * 16 * RS * 2);
            ldsm4(ah[mt], ao + OFF_AHI);
            ldsm4(al[mt], ao + OFF_ALO);
        }

        #pragma unroll
        for (int hf = 0; hf < 2; hf++) {
            uint32_t bh[4][2], bl[4][2];
            #pragma unroll
            for (int nt2 = 0; nt2 < 2; nt2++) {
                uint32_t bo = stb + aoffB
                            + (uint32_t)((hf * 32 + nt2 * 16) * RS * 2);
                uint32_t r[4];
                ldsm4(r, bo + OFF_BHI);
                bh[nt2 * 2][0] = r[0]; bh[nt2 * 2][1] = r[1];
                bh[nt2 * 2 + 1][0] = r[2]; bh[nt2 * 2 + 1][1] = r[3];
                ldsm4(r, bo + OFF_BLO);
                bl[nt2 * 2][0] = r[0]; bl[nt2 * 2][1] = r[1];
                bl[nt2 * 2 + 1][0] = r[2]; bl[nt2 * 2 + 1][1] = r[3];
            }
            #pragma unroll
            for (int mt = 0; mt < 2; mt++)
                #pragma unroll
                for (int nt = 0; nt < 4; nt++) {
                    float* d = acc[mt][hf * 4 + nt];
                    mma16816(d, ah[mt], bh[nt]);
                    mma16816(d, ah[mt], bl[nt]);
                    mma16816(d, al[mt], bh[nt]);
                }
        }
        __syncthreads();
    }

    // ---- epilogue ----------------------------------------------------------
    const long ccol0 = rowB0 + nw * 64 + 2 * (l & 3);
    #pragma unroll
    for (int mt = 0; mt < 2; mt++) {
        const long row = rowA0 + mw * 32 + mt * 16 + (l >> 2);
        #pragma unroll
        for (int nt = 0; nt < 8; nt++) {
            const float* d = acc[mt][nt];
            long col = ccol0 + nt * 8;
            *(float2*)(C + row * N + col) = make_float2(d[0], d[1]);
            *(float2*)(C + (row + 8) * N + col) = make_float2(d[2], d[3]);
        }
    }
}

// ------------------------- fp32 -> bf16 hi/lo split -------------------------
__global__ void __launch_bounds__(256)
split_kernel(const float* __restrict__ src, __nv_bfloat16* __restrict__ hi,
             __nv_bfloat16* __restrict__ lo, int n4)
{
    int i = blockIdx.x * blockDim.x + threadIdx.x;
    if (i >= n4) return;
    float4 v = ((const float4*)src)[i];
    union { __nv_bfloat16 b[4]; uint2 u; } Hv, Lv;
    float f[4] = {v.x, v.y, v.z, v.w};
    #pragma unroll
    for (int j = 0; j < 4; j++) {
        __nv_bfloat16 h = __float2bfloat16(f[j]);
        Hv.b[j] = h;
        Lv.b[j] = __float2bfloat16(f[j] - __bfloat162float(h));
    }
    ((uint2*)hi)[i] = Hv.u;
    ((uint2*)lo)[i] = Lv.u;
}

// ------------------------- RoPE + feature map -------------------------------
__global__ void __launch_bounds__(256)
rope_feat_kernel(const float* __restrict__ qkv,
                 float* __restrict__ qf, float* __restrict__ kf)
{
    int idx = blockIdx.x * blockDim.x + threadIdx.x;
    int i = idx & 31;
    int t = (idx >> 5) & (T_ - 1);
    int pair = idx >> 17;
    int b = pair >> 4;
    int h = pair & 15;

    size_t basei = ((size_t)(b * T_ + t)) * (3 * D_) + h * HD_;
    float qe = qkv[basei + i];
    float qo = qkv[basei + i + 32];
    float ke = qkv[basei + D_ + i];
    float ko = qkv[basei + D_ + i + 32];

    float ang = (float)t * c_invfreq[i];
    float s, c;
    sincosf(ang, &s, &c);

    float qre = qe * c - qo * s;
    float qro = qe * s + qo * c;
    float kre = ke * c - ko * s;
    float kro = ke * s + ko * c;

    const float scale = 0.125f;
    qre *= scale; qro *= scale;

    float fqe = qre > 0.0f ? qre + 1.0f : expm1f(qre) + 1.0f;
    float fqo = qro > 0.0f ? qro + 1.0f : expm1f(qro) + 1.0f;
    float fke = kre > 0.0f ? kre + 1.0f : expm1f(kre) + 1.0f;
    float fko = kro > 0.0f ? kro + 1.0f : expm1f(kro) + 1.0f;

    size_t ob = ((size_t)pair * T_ + t) * HD_;
    qf[ob + i]      = fqe;
    qf[ob + i + 32] = fqo;
    kf[ob + i]      = fke;
    kf[ob + i + 32] = fko;
}

// ------------------------- kv = K^T V, k_sum (partials) ---------------------
__global__ void __launch_bounds__(256)
kv_ksum_kernel(const float* __restrict__ kf, const float* __restrict__ qkv,
               float* __restrict__ kvpart, float* __restrict__ kspart)
{
    __shared__ float ks[32][64];
    __shared__ float vs[32][64];

    const int pair = blockIdx.y;
    const int chunk = blockIdx.x;
    const int b = pair >> 4;
    const int h = pair & 15;
    const int tid = threadIdx.x;
    const int tx = tid & 15;
    const int ty = tid >> 4;

    const float* kbase = kf + ((size_t)pair * T_ + chunk * ROWS_PER_CHUNK) * HD_;
    const float* vbase = qkv + ((size_t)(b * T_ + chunk * ROWS_PER_CHUNK)) * (3 * D_)
                         + 2 * D_ + h * HD_;

    float acc[4][4];
    #pragma unroll
    for (int i = 0; i < 4; i++)
        #pragma unroll
        for (int j = 0; j < 4; j++) acc[i][j] = 0.0f;
    float ksl[4] = {0.0f, 0.0f, 0.0f, 0.0f};

    for (int tile = 0; tile < ROWS_PER_CHUNK / 32; tile++) {
        #pragma unroll
        for (int lp = 0; lp < 2; lp++) {
            int fi = tid + lp * 256;
            int row = fi >> 4;
            int c4 = (fi & 15) * 4;
            *(float4*)&ks[row][c4] =
                *(const float4*)(kbase + (size_t)(tile * 32 + row) * HD_ + c4);
            *(float4*)&vs[row][c4] =
                *(const float4*)(vbase + (size_t)(tile * 32 + row) * (3 * D_) + c4);
        }
        __syncthreads();

        #pragma unroll
        for (int r = 0; r < 32; r++) {
            float ka[4], va[4];
            *(float4*)ka = *(const float4*)&ks[r][ty * 4];
            *(float4*)va = *(const float4*)&vs[r][tx * 4];
            #pragma unroll
            for (int i = 0; i < 4; i++)
                #pragma unroll
                for (int j = 0; j < 4; j++)
                    acc[i][j] = fmaf(ka[i], va[j], acc[i][j]);
            if (ty == 0) {
                #pragma unroll
                for (int j = 0; j < 4; j++)
                    ksl[j] += ks[r][tx * 4 + j];
            }
        }
        __syncthreads();
    }

    float* kvp = kvpart + (size_t)chunk * (PAIRS * HD_ * HD_) + (size_t)pair * HD_ * HD_;
    #pragma unroll
    for (int i = 0; i < 4; i++)
        #pragma unroll
        for (int j = 0; j < 4; j++)
            kvp[(ty * 4 + i) * HD_ + tx * 4 + j] = acc[i][j];
    if (ty == 0) {
        float* ksp = kspart + (size_t)chunk * (PAIRS * HD_) + pair * HD_;
        #pragma unroll
        for (int j = 0; j < 4; j++) ksp[tx * 4 + j] = ksl[j];
    }
}

__global__ void __launch_bounds__(256)
reduce_kv_kernel(const float* __restrict__ kvpart, const float* __restrict__ kspart,
                 float* __restrict__ kv, float* __restrict__ ksum)
{
    int i = blockIdx.x * blockDim.x + threadIdx.x;
    float s = 0.0f;
    #pragma unroll
    for (int c = 0; c < NCHUNK; c++)
        s += kvpart[(size_t)c * (PAIRS * HD_ * HD_) + i];
    kv[i] = s;
    if (i < PAIRS * HD_) {
        float s2 = 0.0f;
        #pragma unroll
        for (int c = 0; c < NCHUNK; c++)
            s2 += kspart[(size_t)c * (PAIRS * HD_) + i];
        ksum[i] = s2;
    }
}

// ------------------------- out = (Q kv) / max(Q.ksum, 1e-6) -----------------
__global__ void __launch_bounds__(256)
attn_out_kernel(const float* __restrict__ qf, const float* __restrict__ kv,
                const float* __restrict__ ksum, float* __restrict__ attn)
{
    __shared__ float kv_s[HD_][HD_];
    __shared__ float q_s[32][HD_];
    __shared__ float ksum_s[HD_];

    const int pair = blockIdx.y;
    const int t0 = blockIdx.x * 32;
    const int b = pair >> 4;
    const int h = pair & 15;
    const int tid = threadIdx.x;
    const int row = tid >> 3;
    const int tx = tid & 7;

    const float4* kvp = (const float4*)(kv + (size_t)pair * HD_ * HD_);
    #pragma unroll
    for (int lp = 0; lp < 4; lp++)
        ((float4*)kv_s)[tid + lp * 256] = kvp[tid + lp * 256];
    if (tid < 16)
        ((float4*)ksum_s)[tid] = ((const float4*)(ksum + pair * HD_))[tid];
    const float4* qp = (const float4*)(qf + ((size_t)pair * T_ + t0) * HD_);
    #pragma unroll
    for (int lp = 0; lp < 2; lp++)
        ((float4*)q_s)[tid + lp * 256] = qp[tid + lp * 256];
    __syncthreads();

    float acc[8] = {0, 0, 0, 0, 0, 0, 0, 0};
    float den = 0.0f;
    #pragma unroll
    for (int d = 0; d < HD_; d++) {
        float qd = q_s[row][d];
        den = fmaf(qd, ksum_s[d], den);
        float4 k0 = *(const float4*)&kv_s[d][tx * 8];
        float4 k1 = *(const float4*)&kv_s[d][tx * 8 + 4];
        acc[0] = fmaf(qd, k0.x, acc[0]);
        acc[1] = fmaf(qd, k0.y, acc[1]);
        acc[2] = fmaf(qd, k0.z, acc[2]);
        acc[3] = fmaf(qd, k0.w, acc[3]);
        acc[4] = fmaf(qd, k1.x, acc[4]);
        acc[5] = fmaf(qd, k1.y, acc[5]);
        acc[6] = fmaf(qd, k1.z, acc[6]);
        acc[7] = fmaf(qd, k1.w, acc[7]);
    }
    float inv = 1.0f / fmaxf(den, 1e-6f);

    float* op = attn + ((size_t)(b * T_ + t0 + row)) * D_ + h * HD_ + tx * 8;
    *(float4*)op = make_float4(acc[0] * inv, acc[1] * inv, acc[2] * inv, acc[3] * inv);
    *(float4*)(op + 4) = make_float4(acc[4] * inv, acc[5] * inv, acc[6] * inv, acc[7] * inv);
}

// ------------------------- launch ------------------------------------------
static float* sym_addr_f(const void* symbol)
{
    void* p = nullptr;
    cudaGetSymbolAddress(&p, symbol);
    return (float*)p;
}
static __nv_bfloat16* sym_addr_b(const void* symbol)
{
    void* p = nullptr;
    cudaGetSymbolAddress(&p, symbol);
    return (__nv_bfloat16*)p;
}

extern "C" void kernel_launch(void* const* d_in, const int* in_sizes, int n_in,
                              void* d_out, int out_size)
{
    (void)in_sizes; (void)n_in; (void)out_size;
    const float* x     = (const float*)d_in[0];   // [B,T,D]
    const float* w_qkv = (const float*)d_in[1];   // [3D,D]
    const float* w_out = (const float*)d_in[2];   // [D,D]
    float* out = (float*)d_out;                   // [B,T,D]

    float* qkv   = sym_addr_f(g_qkv);
    float* qf    = sym_addr_f(g_qf);
    float* kf    = sym_addr_f(g_kf);
    float* attn  = sym_addr_f(g_attn);
    float* kvprt = sym_addr_f(g_kvpart);
    float* ksprt = sym_addr_f(g_kspart);
    float* kv    = sym_addr_f(g_kv);
    float* ksum  = sym_addr_f(g_ksum);
    __nv_bfloat16* ahi = sym_addr_b(g_ahi);
    __nv_bfloat16* alo = sym_addr_b(g_alo);
    __nv_bfloat16* bhi = sym_addr_b(g_bhi);
    __nv_bfloat16* blo = sym_addr_b(g_blo);

    // 1) split x and w_qkv into bf16 hi/lo
    split_kernel<<<(M_ * D_ / 4) / 256, 256>>>(x, ahi, alo, M_ * D_ / 4);
    split_kernel<<<(3 * D_ * D_ / 4) / 256, 256>>>(w_qkv, bhi, blo, 3 * D_ * D_ / 4);

    // 2) qkv = x @ w_qkv^T  [16384, 3072] via mma.sync
    gemm_mma<<<dim3(3 * D_ / 128, M_ / 128), 256>>>(ahi, alo, bhi, blo, qkv, 3 * D_);

    // 3) RoPE + ELU feature map
    rope_feat_kernel<<<(PAIRS * T_ * 32) / 256, 256>>>(qkv, qf, kf);

    // 4) kv = K^T V and k_sum
    kv_ksum_kernel<<<dim3(NCHUNK, PAIRS), 256>>>(kf, qkv, kvprt, ksprt);
    reduce_kv_kernel<<<(PAIRS * HD_ * HD_) / 256, 256>>>(kvprt, ksprt, kv, ksum);

    // 5) out_head = (Q kv) / denom -> [B,T,D]
    attn_out_kernel<<<dim3(T_ / 32, PAIRS), 256>>>(qf, kv, ksum, attn);

    // 6) split attn and w_out, then out = attn @ w_out^T  [16384, 1024]
    split_kernel<<<(M_ * D_ / 4) / 256, 256>>>(attn, ahi, alo, M_ * D_ / 4);
    split_kernel<<<(D_ * D_ / 4) / 256, 256>>>(w_out, bhi, blo, D_ * D_ / 4);
    gemm_mma<<<dim3(D_ / 128, M_ / 128), 256>>>(ahi, alo, bhi, blo, out, D_);
}

// round 6
// speedup vs baseline: 2.1469x; 1.2113x over previous
#include <cuda_runtime.h>
#include <cuda_bf16.h>
#include <math.h>
#include <stdint.h>

// ---------------------------------------------------------------------------
// LinearSelfAttention, Round 5 (re-bench; prior attempt hit infra failure):
// mma.sync bf16 hi/lo 3-pass GEMMs, 4-stage cp.async pipeline (k16 steps,
// RS=24 aligned layout), fused attn->bf16 split, sincos LUT.
// Shapes: B=4, T=4096, D=1024, H=16, hd=64.
// ---------------------------------------------------------------------------

#define B_   4
#define T_   4096
#define D_   1024
#define H_   16
#define HD_  64
#define M_   (B_ * T_)            // 16384
#define PAIRS (B_ * H_)           // 64
#define NCHUNK 16
#define ROWS_PER_CHUNK (T_ / NCHUNK)
#define GK 1024

// ------------------------- scratch (device globals) ------------------------
__device__ float g_qkv[(size_t)M_ * 3 * D_];           // 192 MB
__device__ float g_qf[(size_t)PAIRS * T_ * HD_];       // 64 MB
__device__ float g_kf[(size_t)PAIRS * T_ * HD_];       // 64 MB
__device__ float g_kvpart[(size_t)NCHUNK * PAIRS * HD_ * HD_];
__device__ float g_kspart[(size_t)NCHUNK * PAIRS * HD_];
__device__ float g_kv[(size_t)PAIRS * HD_ * HD_];
__device__ float g_ksum[(size_t)PAIRS * HD_];
__device__ float g_cost[(size_t)T_ * 32];
__device__ float g_sint[(size_t)T_ * 32];
__device__ __nv_bfloat16 g_ahi[(size_t)M_ * D_];       // 32 MB
__device__ __nv_bfloat16 g_alo[(size_t)M_ * D_];       // 32 MB
__device__ __nv_bfloat16 g_bhi[(size_t)3 * D_ * D_];   // 6 MB
__device__ __nv_bfloat16 g_blo[(size_t)3 * D_ * D_];   // 6 MB

__constant__ float c_invfreq[32] = {
    1.0f, 0.7498942093324559f, 0.5623413251903491f, 0.4216965034285822f,
    0.31622776601683794f, 0.23713737056616552f, 0.1778279410038923f,
    0.13335214321633242f,
    0.1f, 0.07498942093324558f, 0.05623413251903491f, 0.04216965034285822f,
    0.03162277660168379f, 0.023713737056616554f, 0.01778279410038923f,
    0.013335214321633242f,
    0.01f, 0.007498942093324559f, 0.005623413251903491f, 0.004216965034285822f,
    0.0031622776601683794f, 0.0023713737056616554f, 0.001778279410038923f,
    0.0013335214321633242f,
    0.001f, 0.0007498942093324559f, 0.0005623413251903491f,
    0.0004216965034285822f, 0.00031622776601683794f, 0.00023713737056616554f,
    0.0001778279410038923f, 0.00013335214321633243f
};

// ------------------------- PTX helpers --------------------------------------
__device__ __forceinline__ uint32_t smem_u32(const void* p) {
    uint32_t a;
    asm("{ .reg .u64 t; cvta.to.shared.u64 t, %1; cvt.u32.u64 %0, t; }"
        : "=r"(a) : "l"(p));
    return a;
}
__device__ __forceinline__ void cpasync16(uint32_t s, const void* g) {
    asm volatile("cp.async.cg.shared.global [%0], [%1], 16;" :: "r"(s), "l"(g));
}
#define CP_COMMIT() asm volatile("cp.async.commit_group;" ::: "memory")
#define CP_WAIT2()  asm volatile("cp.async.wait_group 2;" ::: "memory")

__device__ __forceinline__ void ldsm4(uint32_t* r, uint32_t addr) {
    asm volatile("ldmatrix.sync.aligned.m8n8.x4.shared.b16 {%0,%1,%2,%3}, [%4];"
        : "=r"(r[0]), "=r"(r[1]), "=r"(r[2]), "=r"(r[3]) : "r"(addr));
}
__device__ __forceinline__ void mma16816(float* d, const uint32_t* a,
                                         const uint32_t* b) {
    asm volatile("mma.sync.aligned.m16n8k16.row.col.f32.bf16.bf16.f32 "
        "{%0,%1,%2,%3}, {%4,%5,%6,%7}, {%8,%9}, {%0,%1,%2,%3};"
        : "+f"(d[0]), "+f"(d[1]), "+f"(d[2]), "+f"(d[3])
        : "r"(a[0]), "r"(a[1]), "r"(a[2]), "r"(a[3]), "r"(b[0]), "r"(b[1]));
}

// ------------------------- MMA GEMM: C = A * B^T ----------------------------
// Block 128x128, 8 warps (4M x 2N), warp tile 32x64, K-step 16, 4 stages.
// RS=24 bf16 (48 B rows): cp.async dst 16B-aligned, ldmatrix conflict-free.
#define RS 24
#define OPB (128 * RS * 2)            // 6144 B per operand tile
#define STAGE_B (4 * OPB)             // 24576 B per stage
#define NSTAGE 4
#define GEMM_SMEM (NSTAGE * STAGE_B)  // 98304 B  -> 2 CTAs/SM

__global__ void __launch_bounds__(256, 2)
gemm_mma(const __nv_bfloat16* __restrict__ Ahi, const __nv_bfloat16* __restrict__ Alo,
         const __nv_bfloat16* __restrict__ Bhi, const __nv_bfloat16* __restrict__ Blo,
         float* __restrict__ C, int N)
{
    extern __shared__ __nv_bfloat16 smem[];

    const int tid = threadIdx.x;
    const int l = tid & 31;
    const int w = tid >> 5;
    const int mw = w >> 1;                 // 0..3
    const int nw = w & 1;                  // 0..1
    const long rowA0 = (long)blockIdx.y * 128;
    const long rowB0 = (long)blockIdx.x * 128;

    // ---- loader: each thread copies 16B per operand per stage -------------
    const int lrow = tid >> 1;             // 0..127
    const int lhalf = (tid & 1) * 8;       // 0 or 8 (bf16 elems)
    const __nv_bfloat16* gsrc[4] = {
        Ahi + (rowA0 + lrow) * GK + lhalf,
        Alo + (rowA0 + lrow) * GK + lhalf,
        Bhi + (rowB0 + lrow) * GK + lhalf,
        Blo + (rowB0 + lrow) * GK + lhalf };
    const uint32_t sbase = smem_u32(&smem[0]);
    const uint32_t soff = (uint32_t)((lrow * RS + lhalf) * 2);   // 16B aligned

    float acc[2][8][4];
    #pragma unroll
    for (int i = 0; i < 2; i++)
        #pragma unroll
        for (int j = 0; j < 8; j++)
            #pragma unroll
            for (int k = 0; k < 4; k++) acc[i][j][k] = 0.0f;

    // ldmatrix offsets within a stage
    const uint32_t aoffA = (uint32_t)(((mw * 32 + (l & 15)) * RS + (l >> 4) * 8) * 2);
    const uint32_t aoffB = (uint32_t)((((nw * 64 + (l & 7) + ((l >> 4) << 3)) * RS
                                       + ((l >> 3) & 1) * 8)) * 2);

    const int NIT = GK / 16;               // 64

    // ---- prefetch stages 0..2 ---------------------------------------------
    #pragma unroll
    for (int s = 0; s < NSTAGE - 1; s++) {
        const uint32_t dst = sbase + s * STAGE_B;
        #pragma unroll
        for (int o = 0; o < 4; o++)
            cpasync16(dst + o * OPB + soff, gsrc[o] + s * 16);
        CP_COMMIT();
    }

    for (int c = 0; c < NIT; c++) {
        CP_WAIT2();                        // stage c resident (<=2 groups left)
        __syncthreads();                   // data visible; slot (c-1)%4 free

        const int pf = c + NSTAGE - 1;
        if (pf < NIT) {
            const uint32_t dst = sbase + (pf & (NSTAGE - 1)) * STAGE_B;
            #pragma unroll
            for (int o = 0; o < 4; o++)
                cpasync16(dst + o * OPB + soff, gsrc[o] + pf * 16);
        }
        CP_COMMIT();                       // unconditional: keeps pending == 3

        const uint32_t stb = sbase + (c & (NSTAGE - 1)) * STAGE_B;

        uint32_t ah[2][4], al[2][4];
        #pragma unroll
        for (int mt = 0; mt < 2; mt++) {
            uint32_t ao = stb + aoffA + (uint32_t)(mt * 16 * RS * 2);
            ldsm4(ah[mt], ao);
            ldsm4(al[mt], ao + OPB);
        }

        #pragma unroll
        for (int hf = 0; hf < 2; hf++) {
            uint32_t bh[4][2], bl[4][2];
            #pragma unroll
            for (int nt2 = 0; nt2 < 2; nt2++) {
                uint32_t bo = stb + aoffB
                            + (uint32_t)((hf * 32 + nt2 * 16) * RS * 2) + 2 * OPB;
                uint32_t r[4];
                ldsm4(r, bo);
                bh[nt2 * 2][0] = r[0]; bh[nt2 * 2][1] = r[1];
                bh[nt2 * 2 + 1][0] = r[2]; bh[nt2 * 2 + 1][1] = r[3];
                ldsm4(r, bo + OPB);
                bl[nt2 * 2][0] = r[0]; bl[nt2 * 2][1] = r[1];
                bl[nt2 * 2 + 1][0] = r[2]; bl[nt2 * 2 + 1][1] = r[3];
            }
            #pragma unroll
            for (int mt = 0; mt < 2; mt++)
                #pragma unroll
                for (int nt = 0; nt < 4; nt++) {
                    float* d = acc[mt][hf * 4 + nt];
                    mma16816(d, ah[mt], bh[nt]);
                    mma16816(d, ah[mt], bl[nt]);
                    mma16816(d, al[mt], bh[nt]);
                }
        }
    }

    // ---- epilogue ----------------------------------------------------------
    const long ccol0 = rowB0 + nw * 64 + 2 * (l & 3);
    #pragma unroll
    for (int mt = 0; mt < 2; mt++) {
        const long row = rowA0 + mw * 32 + mt * 16 + (l >> 2);
        #pragma unroll
        for (int nt = 0; nt < 8; nt++) {
            const float* d = acc[mt][nt];
            long col = ccol0 + nt * 8;
            *(float2*)(C + row * N + col) = make_float2(d[0], d[1]);
            *(float2*)(C + (row + 8) * N + col) = make_float2(d[2], d[3]);
        }
    }
}

// ------------------------- fp32 -> bf16 hi/lo split -------------------------
__global__ void __launch_bounds__(256)
split_kernel(const float* __restrict__ src, __nv_bfloat16* __restrict__ hi,
             __nv_bfloat16* __restrict__ lo, int n4)
{
    int i = blockIdx.x * blockDim.x + threadIdx.x;
    if (i >= n4) return;
    float4 v = ((const float4*)src)[i];
    union { __nv_bfloat16 b[4]; uint2 u; } Hv, Lv;
    float f[4] = {v.x, v.y, v.z, v.w};
    #pragma unroll
    for (int j = 0; j < 4; j++) {
        __nv_bfloat16 h = __float2bfloat16(f[j]);
        Hv.b[j] = h;
        Lv.b[j] = __float2bfloat16(f[j] - __bfloat162float(h));
    }
    ((uint2*)hi)[i] = Hv.u;
    ((uint2*)lo)[i] = Lv.u;
}

// ------------------------- sincos table -------------------------------------
__global__ void __launch_bounds__(256)
sincos_table_kernel(float* __restrict__ cost, float* __restrict__ sint)
{
    int idx = blockIdx.x * blockDim.x + threadIdx.x;   // T*32
    int t = idx >> 5;
    int i = idx & 31;
    float s, c;
    sincosf((float)t * c_invfreq[i], &s, &c);
    cost[idx] = c;
    sint[idx] = s;
}

// ------------------------- RoPE + feature map -------------------------------
__global__ void __launch_bounds__(256)
rope_feat_kernel(const float* __restrict__ qkv,
                 const float* __restrict__ cost, const float* __restrict__ sint,
                 float* __restrict__ qf, float* __restrict__ kf)
{
    int idx = blockIdx.x * blockDim.x + threadIdx.x;
    int i = idx & 31;
    int t = (idx >> 5) & (T_ - 1);
    int pair = idx >> 17;
    int b = pair >> 4;
    int h = pair & 15;

    size_t basei = ((size_t)(b * T_ + t)) * (3 * D_) + h * HD_;
    float qe = qkv[basei + i];
    float qo = qkv[basei + i + 32];
    float ke = qkv[basei + D_ + i];
    float ko = qkv[basei + D_ + i + 32];

    float c = cost[t * 32 + i];
    float s = sint[t * 32 + i];

    float qre = qe * c - qo * s;
    float qro = qe * s + qo * c;
    float kre = ke * c - ko * s;
    float kro = ke * s + ko * c;

    const float scale = 0.125f;
    qre *= scale; qro *= scale;

    float fqe = qre > 0.0f ? qre + 1.0f : expm1f(qre) + 1.0f;
    float fqo = qro > 0.0f ? qro + 1.0f : expm1f(qro) + 1.0f;
    float fke = kre > 0.0f ? kre + 1.0f : expm1f(kre) + 1.0f;
    float fko = kro > 0.0f ? kro + 1.0f : expm1f(kro) + 1.0f;

    size_t ob = ((size_t)pair * T_ + t) * HD_;
    qf[ob + i]      = fqe;
    qf[ob + i + 32] = fqo;
    kf[ob + i]      = fke;
    kf[ob + i + 32] = fko;
}

// ------------------------- kv = K^T V, k_sum (partials) ---------------------
__global__ void __launch_bounds__(256)
kv_ksum_kernel(const float* __restrict__ kf, const float* __restrict__ qkv,
               float* __restrict__ kvpart, float* __restrict__ kspart)
{
    __shared__ float ks[32][64];
    __shared__ float vs[32][64];

    const int pair = blockIdx.y;
    const int chunk = blockIdx.x;
    const int b = pair >> 4;
    const int h = pair & 15;
    const int tid = threadIdx.x;
    const int tx = tid & 15;
    const int ty = tid >> 4;

    const float* kbase = kf + ((size_t)pair * T_ + chunk * ROWS_PER_CHUNK) * HD_;
    const float* vbase = qkv + ((size_t)(b * T_ + chunk * ROWS_PER_CHUNK)) * (3 * D_)
                         + 2 * D_ + h * HD_;

    float acc[4][4];
    #pragma unroll
    for (int i = 0; i < 4; i++)
        #pragma unroll
        for (int j = 0; j < 4; j++) acc[i][j] = 0.0f;
    float ksl[4] = {0.0f, 0.0f, 0.0f, 0.0f};

    for (int tile = 0; tile < ROWS_PER_CHUNK / 32; tile++) {
        #pragma unroll
        for (int lp = 0; lp < 2; lp++) {
            int fi = tid + lp * 256;
            int row = fi >> 4;
            int c4 = (fi & 15) * 4;
            *(float4*)&ks[row][c4] =
                *(const float4*)(kbase + (size_t)(tile * 32 + row) * HD_ + c4);
            *(float4*)&vs[row][c4] =
                *(const float4*)(vbase + (size_t)(tile * 32 + row) * (3 * D_) + c4);
        }
        __syncthreads();

        #pragma unroll
        for (int r = 0; r < 32; r++) {
            float ka[4], va[4];
            *(float4*)ka = *(const float4*)&ks[r][ty * 4];
            *(float4*)va = *(const float4*)&vs[r][tx * 4];
            #pragma unroll
            for (int i = 0; i < 4; i++)
                #pragma unroll
                for (int j = 0; j < 4; j++)
                    acc[i][j] = fmaf(ka[i], va[j], acc[i][j]);
            if (ty == 0) {
                #pragma unroll
                for (int j = 0; j < 4; j++)
                    ksl[j] += ks[r][tx * 4 + j];
            }
        }
        __syncthreads();
    }

    float* kvp = kvpart + (size_t)chunk * (PAIRS * HD_ * HD_) + (size_t)pair * HD_ * HD_;
    #pragma unroll
    for (int i = 0; i < 4; i++)
        #pragma unroll
        for (int j = 0; j < 4; j++)
            kvp[(ty * 4 + i) * HD_ + tx * 4 + j] = acc[i][j];
    if (ty == 0) {
        float* ksp = kspart + (size_t)chunk * (PAIRS * HD_) + pair * HD_;
        #pragma unroll
        for (int j = 0; j < 4; j++) ksp[tx * 4 + j] = ksl[j];
    }
}

__global__ void __launch_bounds__(256)
reduce_kv_kernel(const float* __restrict__ kvpart, const float* __restrict__ kspart,
                 float* __restrict__ kv, float* __restrict__ ksum)
{
    int i = blockIdx.x * blockDim.x + threadIdx.x;
    float s = 0.0f;
    #pragma unroll
    for (int c = 0; c < NCHUNK; c++)
        s += kvpart[(size_t)c * (PAIRS * HD_ * HD_) + i];
    kv[i] = s;
    if (i < PAIRS * HD_) {
        float s2 = 0.0f;
        #pragma unroll
        for (int c = 0; c < NCHUNK; c++)
            s2 += kspart[(size_t)c * (PAIRS * HD_) + i];
        ksum[i] = s2;
    }
}

// ---------------- out = (Q kv)/denom, fused bf16 hi/lo output ---------------
__global__ void __launch_bounds__(256)
attn_out_kernel(const float* __restrict__ qf, const float* __restrict__ kv,
                const float* __restrict__ ksum,
                __nv_bfloat16* __restrict__ ahi, __nv_bfloat16* __restrict__ alo)
{
    __shared__ float kv_s[HD_][HD_];
    __shared__ float q_s[32][HD_];
    __shared__ float ksum_s[HD_];

    const int pair = blockIdx.y;
    const int t0 = blockIdx.x * 32;
    const int b = pair >> 4;
    const int h = pair & 15;
    const int tid = threadIdx.x;
    const int row = tid >> 3;
    const int tx = tid & 7;

    const float4* kvp = (const float4*)(kv + (size_t)pair * HD_ * HD_);
    #pragma unroll
    for (int lp = 0; lp < 4; lp++)
        ((float4*)kv_s)[tid + lp * 256] = kvp[tid + lp * 256];
    if (tid < 16)
        ((float4*)ksum_s)[tid] = ((const float4*)(ksum + pair * HD_))[tid];
    const float4* qp = (const float4*)(qf + ((size_t)pair * T_ + t0) * HD_);
    #pragma unroll
    for (int lp = 0; lp < 2; lp++)
        ((float4*)q_s)[tid + lp * 256] = qp[tid + lp * 256];
    __syncthreads();

    float acc[8] = {0, 0, 0, 0, 0, 0, 0, 0};
    float den = 0.0f;
    #pragma unroll
    for (int d = 0; d < HD_; d++) {
        float qd = q_s[row][d];
        den = fmaf(qd, ksum_s[d], den);
        float4 k0 = *(const float4*)&kv_s[d][tx * 8];
        float4 k1 = *(const float4*)&kv_s[d][tx * 8 + 4];
        acc[0] = fmaf(qd, k0.x, acc[0]);
        acc[1] = fmaf(qd, k0.y, acc[1]);
        acc[2] = fmaf(qd, k0.z, acc[2]);
        acc[3] = fmaf(qd, k0.w, acc[3]);
        acc[4] = fmaf(qd, k1.x, acc[4]);
        acc[5] = fmaf(qd, k1.y, acc[5]);
        acc[6] = fmaf(qd, k1.z, acc[6]);
        acc[7] = fmaf(qd, k1.w, acc[7]);
    }
    float inv = 1.0f / fmaxf(den, 1e-6f);

    union { __nv_bfloat16 b[8]; uint4 u; } Hv, Lv;
    #pragma unroll
    for (int j = 0; j < 8; j++) {
        float v = acc[j] * inv;
        __nv_bfloat16 hh = __float2bfloat16(v);
        Hv.b[j] = hh;
        Lv.b[j] = __float2bfloat16(v - __bfloat162float(hh));
    }
    size_t off = ((size_t)(b * T_ + t0 + row)) * D_ + h * HD_ + tx * 8;
    *(uint4*)(ahi + off) = Hv.u;
    *(uint4*)(alo + off) = Lv.u;
}

// ------------------------- launch ------------------------------------------
static float* sym_addr_f(const void* symbol)
{
    void* p = nullptr;
    cudaGetSymbolAddress(&p, symbol);
    return (float*)p;
}
static __nv_bfloat16* sym_addr_b(const void* symbol)
{
    void* p = nullptr;
    cudaGetSymbolAddress(&p, symbol);
    return (__nv_bfloat16*)p;
}

extern "C" void kernel_launch(void* const* d_in, const int* in_sizes, int n_in,
                              void* d_out, int out_size)
{
    (void)in_sizes; (void)n_in; (void)out_size;
    const float* x     = (const float*)d_in[0];   // [B,T,D]
    const float* w_qkv = (const float*)d_in[1];   // [3D,D]
    const float* w_out = (const float*)d_in[2];   // [D,D]
    float* out = (float*)d_out;                   // [B,T,D]

    float* qkv   = sym_addr_f(g_qkv);
    float* qf    = sym_addr_f(g_qf);
    float* kf    = sym_addr_f(g_kf);
    float* kvprt = sym_addr_f(g_kvpart);
    float* ksprt = sym_addr_f(g_kspart);
    float* kv    = sym_addr_f(g_kv);
    float* ksum  = sym_addr_f(g_ksum);
    float* cost  = sym_addr_f(g_cost);
    float* sint  = sym_addr_f(g_sint);
    __nv_bfloat16* ahi = sym_addr_b(g_ahi);
    __nv_bfloat16* alo = sym_addr_b(g_alo);
    __nv_bfloat16* bhi = sym_addr_b(g_bhi);
    __nv_bfloat16* blo = sym_addr_b(g_blo);

    cudaFuncSetAttribute(gemm_mma, cudaFuncAttributeMaxDynamicSharedMemorySize,
                         GEMM_SMEM);

    // 0) sincos LUT
    sincos_table_kernel<<<(T_ * 32) / 256, 256>>>(cost, sint);

    // 1) split x and w_qkv into bf16 hi/lo
    split_kernel<<<(M_ * D_ / 4) / 256, 256>>>(x, ahi, alo, M_ * D_ / 4);
    split_kernel<<<(3 * D_ * D_ / 4) / 256, 256>>>(w_qkv, bhi, blo, 3 * D_ * D_ / 4);

    // 2) qkv = x @ w_qkv^T  [16384, 3072]
    gemm_mma<<<dim3(3 * D_ / 128, M_ / 128), 256, GEMM_SMEM>>>(
        ahi, alo, bhi, blo, qkv, 3 * D_);

    // 3) RoPE + ELU feature map
    rope_feat_kernel<<<(PAIRS * T_ * 32) / 256, 256>>>(qkv, cost, sint, qf, kf);

    // 4) kv = K^T V and k_sum
    kv_ksum_kernel<<<dim3(NCHUNK, PAIRS), 256>>>(kf, qkv, kvprt, ksprt);
    reduce_kv_kernel<<<(PAIRS * HD_ * HD_) / 256, 256>>>(kvprt, ksprt, kv, ksum);

    // 5) out_head = (Q kv)/denom -> bf16 hi/lo directly (A of GEMM2)
    attn_out_kernel<<<dim3(T_ / 32, PAIRS), 256>>>(qf, kv, ksum, ahi, alo);

    // 6) split w_out, then out = attn @ w_out^T  [16384, 1024]
    split_kernel<<<(D_ * D_ / 4) / 256, 256>>>(w_out, bhi, blo, D_ * D_ / 4);
    gemm_mma<<<dim3(D_ / 128, M_ / 128), 256, GEMM_SMEM>>>(
        ahi, alo, bhi, blo, out, D_);
}